// round 4
// baseline (speedup 1.0000x reference)
#include <cuda_runtime.h>
#include <cuda_fp16.h>
#include <math.h>

#define NN 50000
#define EE 850000
#define F  128
#define HEADS 4

// ---------------- scratch ----------------
__device__ __half g_hwh[NN * F];    // transformed features (fp16, gather operand)
__device__ float g_feat[NN * F];    // layer output (fp32, next GEMM input)
__device__ float g_als[NN * HEADS];
__device__ float g_ald[NN * HEADS];
__device__ int   g_deg[NN];
__device__ int   g_off[NN + 1];
__device__ int   g_cur[NN];
__device__ int   g_ssrc[EE];

// ---------------- CSR build ----------------
__global__ void zero_deg_kernel(int n) {
    int i = blockIdx.x * blockDim.x + threadIdx.x;
    if (i < n) g_deg[i] = 0;
}

__global__ void hist_kernel(const int* __restrict__ dst, int e) {
    int i = blockIdx.x * blockDim.x + threadIdx.x;
    if (i < e) atomicAdd(&g_deg[dst[i]], 1);
}

__global__ void scan_kernel(int n) {
    __shared__ int wsum[32];
    __shared__ int s_total;
    int t = threadIdx.x, lane = t & 31, wid = t >> 5;
    int carry = 0;
    for (int base = 0; base < n; base += 1024) {
        int idx = base + t;
        int v = (idx < n) ? g_deg[idx] : 0;
        int x = v;
        #pragma unroll
        for (int d = 1; d < 32; d <<= 1) {
            int y = __shfl_up_sync(0xffffffffu, x, d);
            if (lane >= d) x += y;
        }
        if (lane == 31) wsum[wid] = x;
        __syncthreads();
        if (wid == 0) {
            int w = wsum[lane];
            int xs = w;
            #pragma unroll
            for (int d = 1; d < 32; d <<= 1) {
                int y = __shfl_up_sync(0xffffffffu, xs, d);
                if (lane >= d) xs += y;
            }
            wsum[lane] = xs - w;
            if (lane == 31) s_total = xs;
        }
        __syncthreads();
        int excl = carry + wsum[wid] + (x - v);
        if (idx < n) { g_off[idx] = excl; g_cur[idx] = excl; }
        carry += s_total;
        __syncthreads();
    }
    if (t == 0) g_off[n] = carry;
}

__global__ void scatter_kernel(const int* __restrict__ src,
                               const int* __restrict__ dst, int e) {
    int i = blockIdx.x * blockDim.x + threadIdx.x;
    if (i < e) {
        int d = dst[i];
        int p = atomicAdd(&g_cur[d], 1);
        g_ssrc[p] = src[i];
    }
}

// ---------------- f32x2 helpers ----------------
__device__ __forceinline__ unsigned long long ffma2(unsigned long long a,
                                                    unsigned long long b,
                                                    unsigned long long c) {
    unsigned long long d;
    asm("fma.rn.f32x2 %0, %1, %2, %3;" : "=l"(d) : "l"(a), "l"(b), "l"(c));
    return d;
}
__device__ __forceinline__ unsigned long long dup2(float x) {
    unsigned long long d;
    asm("mov.b64 %0, {%1, %1};" : "=l"(d) : "f"(x));
    return d;
}

// ---------------- GEMM: 512 thr, 4x8 micro-tile, BK=16, j-paired f32x2 accs ----------------
__global__ void __launch_bounds__(512)
gemm128_kernel(const float* __restrict__ xext, int use_ext,
               const float* __restrict__ W,
               const float* __restrict__ asrc,
               const float* __restrict__ adst, int n) {
    __shared__ float aT[16][132];
    __shared__ float wT[16][132];
    const float* A = use_ext ? xext : g_feat;
    int t = threadIdx.x;
    int n0 = blockIdx.x * 128;
    int rowg = t >> 4;         // 0..31 -> rows rowg*4..+3
    int colg = t & 15;         // 0..15 -> cols colg*8..+7
    int lrow = t >> 2;         // 0..127
    int lk4  = (t & 3) * 4;    // 0,4,8,12
    bool rvalid = (n0 + lrow) < n;
    const float* arow = A + (size_t)(n0 + lrow) * F;
    const float* wrow = W + (size_t)lrow * F;

    unsigned long long acc2[4][4];
    #pragma unroll
    for (int i = 0; i < 4; i++)
        #pragma unroll
        for (int jp = 0; jp < 4; jp++) acc2[i][jp] = 0ULL;

    float4 av = rvalid ? *(const float4*)(arow + lk4)
                       : make_float4(0.f, 0.f, 0.f, 0.f);
    float4 wv = *(const float4*)(wrow + lk4);

    for (int k0 = 0; k0 < F; k0 += 16) {
        aT[lk4 + 0][lrow] = av.x; aT[lk4 + 1][lrow] = av.y;
        aT[lk4 + 2][lrow] = av.z; aT[lk4 + 3][lrow] = av.w;
        wT[lk4 + 0][lrow] = wv.x; wT[lk4 + 1][lrow] = wv.y;
        wT[lk4 + 2][lrow] = wv.z; wT[lk4 + 3][lrow] = wv.w;
        __syncthreads();
        if (k0 + 16 < F) {
            av = rvalid ? *(const float4*)(arow + k0 + 16 + lk4)
                        : make_float4(0.f, 0.f, 0.f, 0.f);
            wv = *(const float4*)(wrow + k0 + 16 + lk4);
        }
        #pragma unroll
        for (int kk = 0; kk < 16; kk++) {
            float4 a  = *(const float4*)&aT[kk][rowg * 4];
            float4 b0 = *(const float4*)&wT[kk][colg * 8];
            float4 b1 = *(const float4*)&wT[kk][colg * 8 + 4];
            const unsigned long long* bq0 = reinterpret_cast<const unsigned long long*>(&b0);
            const unsigned long long* bq1 = reinterpret_cast<const unsigned long long*>(&b1);
            unsigned long long bp[4] = {bq0[0], bq0[1], bq1[0], bq1[1]};
            unsigned long long ad4[4] = {dup2(a.x), dup2(a.y), dup2(a.z), dup2(a.w)};
            #pragma unroll
            for (int i = 0; i < 4; i++)
                #pragma unroll
                for (int jp = 0; jp < 4; jp++)
                    acc2[i][jp] = ffma2(ad4[i], bp[jp], acc2[i][jp]);
        }
        __syncthreads();
    }

    // unpack: row i holds cols colg*8..+7 contiguously
    float acc[4][8];
    #pragma unroll
    for (int i = 0; i < 4; i++)
        #pragma unroll
        for (int jp = 0; jp < 4; jp++) {
            float2 f = *reinterpret_cast<float2*>(&acc2[i][jp]);
            acc[i][2 * jp] = f.x;
            acc[i][2 * jp + 1] = f.y;
        }

    // store h as fp16
    #pragma unroll
    for (int i = 0; i < 4; i++) {
        int row = n0 + rowg * 4 + i;
        if (row < n) {
            union { __half2 h[4]; float4 f4; } u;
            u.h[0] = __floats2half2_rn(acc[i][0], acc[i][1]);
            u.h[1] = __floats2half2_rn(acc[i][2], acc[i][3]);
            u.h[2] = __floats2half2_rn(acc[i][4], acc[i][5]);
            u.h[3] = __floats2half2_rn(acc[i][6], acc[i][7]);
            *(float4*)(g_hwh + (size_t)row * F + colg * 8) = u.f4;
        }
    }

    // fused attention logits from exact fp32 accumulators
    float4 as0 = *(const float4*)(asrc + colg * 8);
    float4 as1 = *(const float4*)(asrc + colg * 8 + 4);
    float4 ad0 = *(const float4*)(adst + colg * 8);
    float4 ad1 = *(const float4*)(adst + colg * 8 + 4);
    #pragma unroll
    for (int i = 0; i < 4; i++) {
        float ps = acc[i][0] * as0.x + acc[i][1] * as0.y + acc[i][2] * as0.z + acc[i][3] * as0.w
                 + acc[i][4] * as1.x + acc[i][5] * as1.y + acc[i][6] * as1.z + acc[i][7] * as1.w;
        float pd = acc[i][0] * ad0.x + acc[i][1] * ad0.y + acc[i][2] * ad0.z + acc[i][3] * ad0.w
                 + acc[i][4] * ad1.x + acc[i][5] * ad1.y + acc[i][6] * ad1.z + acc[i][7] * ad1.w;
        ps += __shfl_down_sync(0xffffffffu, ps, 2, 4);
        ps += __shfl_down_sync(0xffffffffu, ps, 1, 4);
        pd += __shfl_down_sync(0xffffffffu, pd, 2, 4);
        pd += __shfl_down_sync(0xffffffffu, pd, 1, 4);
        int row = n0 + rowg * 4 + i;
        if ((colg & 3) == 0 && row < n) {
            g_als[row * HEADS + (colg >> 2)] = ps;
            g_ald[row * HEADS + (colg >> 2)] = pd;
        }
    }
}

// ---------------- aggregation: fp32 weights, fp16 gather ----------------
__global__ void agg_kernel(const float* __restrict__ bias,
                           float* __restrict__ outext, int use_ext,
                           int apply_elu, int n) {
    __shared__ float4 s_w[8][32];
    __shared__ int    s_sn[8][32];
    int wip = threadIdx.x >> 5;
    int node = blockIdx.x * 8 + wip;
    if (node >= n) return;
    int lane = threadIdx.x & 31;
    int hd = lane >> 3;
    int j0 = g_off[node], j1 = g_off[node + 1];
    float4 ald = *(const float4*)(g_ald + node * HEADS);
    float4 ssum = make_float4(0.f, 0.f, 0.f, 0.f);
    float4 acc  = make_float4(0.f, 0.f, 0.f, 0.f);

    for (int base = j0; base < j1; base += 32) {
        int j = base + lane;
        float4 w4 = make_float4(0.f, 0.f, 0.f, 0.f);
        int sn = 0;
        if (j < j1) {
            sn = g_ssrc[j];
            float4 al = *(const float4*)(g_als + sn * HEADS);
            float e0 = al.x + ald.x; e0 = fmaxf(e0, 0.2f * e0);
            float e1 = al.y + ald.y; e1 = fmaxf(e1, 0.2f * e1);
            float e2 = al.z + ald.z; e2 = fmaxf(e2, 0.2f * e2);
            float e3 = al.w + ald.w; e3 = fmaxf(e3, 0.2f * e3);
            w4.x = __expf(e0); w4.y = __expf(e1);
            w4.z = __expf(e2); w4.w = __expf(e3);
            ssum.x += w4.x; ssum.y += w4.y; ssum.z += w4.z; ssum.w += w4.w;
        }
        s_sn[wip][lane] = sn;
        s_w[wip][lane]  = w4;
        __syncwarp();
        int cnt = min(32, j1 - base);
        const float* wj = &s_w[wip][0].x;
        #pragma unroll 4
        for (int jj = 0; jj < cnt; jj++) {
            int s = s_sn[wip][jj];
            float wgt = wj[jj * 4 + hd];
            const __half2* hp = (const __half2*)(g_hwh + (size_t)s * F + lane * 4);
            uint2 raw = *(const uint2*)hp;
            float2 f01 = __half22float2(*reinterpret_cast<__half2*>(&raw.x));
            float2 f23 = __half22float2(*reinterpret_cast<__half2*>(&raw.y));
            acc.x = fmaf(wgt, f01.x, acc.x);
            acc.y = fmaf(wgt, f01.y, acc.y);
            acc.z = fmaf(wgt, f23.x, acc.z);
            acc.w = fmaf(wgt, f23.y, acc.w);
        }
        __syncwarp();
    }

    #pragma unroll
    for (int d = 16; d > 0; d >>= 1) {
        ssum.x += __shfl_xor_sync(0xffffffffu, ssum.x, d);
        ssum.y += __shfl_xor_sync(0xffffffffu, ssum.y, d);
        ssum.z += __shfl_xor_sync(0xffffffffu, ssum.z, d);
        ssum.w += __shfl_xor_sync(0xffffffffu, ssum.w, d);
    }
    float sh = (hd == 0) ? ssum.x : (hd == 1) ? ssum.y : (hd == 2) ? ssum.z : ssum.w;
    float inv = 1.f / (sh + 1e-16f);
    float4 bv = *(const float4*)(bias + lane * 4);
    float4 o;
    o.x = fmaf(acc.x, inv, bv.x);
    o.y = fmaf(acc.y, inv, bv.y);
    o.z = fmaf(acc.z, inv, bv.z);
    o.w = fmaf(acc.w, inv, bv.w);
    if (apply_elu) {
        o.x = o.x > 0.f ? o.x : expm1f(o.x);
        o.y = o.y > 0.f ? o.y : expm1f(o.y);
        o.z = o.z > 0.f ? o.z : expm1f(o.z);
        o.w = o.w > 0.f ? o.w : expm1f(o.w);
    }
    float* outp = use_ext ? outext : g_feat;
    *(float4*)(outp + (size_t)node * F + lane * 4) = o;
}

// ---------------- launch ----------------
extern "C" void kernel_launch(void* const* d_in, const int* in_sizes, int n_in,
                              void* d_out, int out_size) {
    const float* x   = (const float*)d_in[0];
    const int*   src = (const int*)d_in[1];
    const int*   dst = (const int*)d_in[2];
    const int n = in_sizes[0] / F;
    const int e = in_sizes[1];

    const int gemm_grid = (n + 127) / 128;
    const int agg_grid  = (n + 7) / 8;

    // gemm0 hoisted so the profiler's fixed sample slot lands on the GEMM
    zero_deg_kernel<<<(n + 255) / 256, 256>>>(n);
    hist_kernel<<<(e + 255) / 256, 256>>>(dst, e);
    scan_kernel<<<1, 1024>>>(n);
    gemm128_kernel<<<gemm_grid, 512>>>(x, 1, (const float*)d_in[3],
                                       (const float*)d_in[4], (const float*)d_in[5], n);
    scatter_kernel<<<(e + 255) / 256, 256>>>(src, dst, e);

    for (int l = 0; l < 3; l++) {
        const float* W    = (const float*)d_in[3 + 4 * l];
        const float* asrc = (const float*)d_in[4 + 4 * l];
        const float* adst = (const float*)d_in[5 + 4 * l];
        const float* b    = (const float*)d_in[6 + 4 * l];
        if (l > 0)
            gemm128_kernel<<<gemm_grid, 512>>>(x, 0, W, asrc, adst, n);
        int last = (l == 2);
        agg_kernel<<<agg_grid, 256>>>(b, (float*)d_out, last, last ? 0 : 1, n);
    }
}

// round 5
// speedup vs baseline: 1.1822x; 1.1822x over previous
#include <cuda_runtime.h>
#include <math.h>

#define NN 50000
#define EE 850000
#define F  128
#define HEADS 4

// ---------------- scratch ----------------
__device__ float g_hw[NN * F];
__device__ float g_feat[NN * F];
__device__ float g_als[NN * HEADS];
__device__ float g_ald[NN * HEADS];
__device__ int   g_deg[NN];
__device__ int   g_off[NN + 1];
__device__ int   g_cur[NN];
__device__ int   g_ssrc[EE];

// ---------------- CSR build ----------------
__global__ void zero_deg_kernel(int n) {
    int i = blockIdx.x * blockDim.x + threadIdx.x;
    if (i < n) g_deg[i] = 0;
}

__global__ void hist_kernel(const int* __restrict__ dst, int e) {
    int i = blockIdx.x * blockDim.x + threadIdx.x;
    if (i < e) atomicAdd(&g_deg[dst[i]], 1);
}

__global__ void scan_kernel(int n) {
    __shared__ int wsum[32];
    __shared__ int s_total;
    int t = threadIdx.x, lane = t & 31, wid = t >> 5;
    int carry = 0;
    for (int base = 0; base < n; base += 1024) {
        int idx = base + t;
        int v = (idx < n) ? g_deg[idx] : 0;
        int x = v;
        #pragma unroll
        for (int d = 1; d < 32; d <<= 1) {
            int y = __shfl_up_sync(0xffffffffu, x, d);
            if (lane >= d) x += y;
        }
        if (lane == 31) wsum[wid] = x;
        __syncthreads();
        if (wid == 0) {
            int w = wsum[lane];
            int xs = w;
            #pragma unroll
            for (int d = 1; d < 32; d <<= 1) {
                int y = __shfl_up_sync(0xffffffffu, xs, d);
                if (lane >= d) xs += y;
            }
            wsum[lane] = xs - w;
            if (lane == 31) s_total = xs;
        }
        __syncthreads();
        int excl = carry + wsum[wid] + (x - v);
        if (idx < n) { g_off[idx] = excl; g_cur[idx] = excl; }
        carry += s_total;
        __syncthreads();
    }
    if (t == 0) g_off[n] = carry;
}

__global__ void scatter_kernel(const int* __restrict__ src,
                               const int* __restrict__ dst, int e) {
    int i = blockIdx.x * blockDim.x + threadIdx.x;
    if (i < e) {
        int d = dst[i];
        int p = atomicAdd(&g_cur[d], 1);
        g_ssrc[p] = src[i];
    }
}

// ---------------- f32x2 helpers ----------------
__device__ __forceinline__ unsigned long long ffma2(unsigned long long a,
                                                    unsigned long long b,
                                                    unsigned long long c) {
    unsigned long long d;
    asm("fma.rn.f32x2 %0, %1, %2, %3;" : "=l"(d) : "l"(a), "l"(b), "l"(c));
    return d;
}
__device__ __forceinline__ unsigned long long dup2(float x) {
    unsigned long long d;
    asm("mov.b64 %0, {%1, %1};" : "=l"(d) : "f"(x));
    return d;
}

// ---------------- GEMM: 256 thr, 8x8 tile, BK=8, DOUBLE-BUFFERED smem ----------------
struct SBuf { float a[8][132]; float w[8][132]; };

__device__ __forceinline__ void gemm_store_slab(SBuf& b, int lrow, int lk4,
                                                const float4& av, const float4& wv) {
    b.a[lk4 + 0][lrow] = av.x; b.a[lk4 + 1][lrow] = av.y;
    b.a[lk4 + 2][lrow] = av.z; b.a[lk4 + 3][lrow] = av.w;
    b.w[lk4 + 0][lrow] = wv.x; b.w[lk4 + 1][lrow] = wv.y;
    b.w[lk4 + 2][lrow] = wv.z; b.w[lk4 + 3][lrow] = wv.w;
}

__device__ __forceinline__ void gemm_compute_slab(const SBuf& b, int rowg, int colg,
                                                  unsigned long long acc2[4][8]) {
    #pragma unroll
    for (int kk = 0; kk < 8; kk++) {
        float4 a0 = *(const float4*)&b.a[kk][rowg * 8];
        float4 a1 = *(const float4*)&b.a[kk][rowg * 8 + 4];
        float4 b0 = *(const float4*)&b.w[kk][colg * 8];
        float4 b1 = *(const float4*)&b.w[kk][colg * 8 + 4];
        const unsigned long long* ap0 = reinterpret_cast<const unsigned long long*>(&a0);
        const unsigned long long* ap1 = reinterpret_cast<const unsigned long long*>(&a1);
        unsigned long long ap[4] = {ap0[0], ap0[1], ap1[0], ap1[1]};
        unsigned long long bd[8] = {dup2(b0.x), dup2(b0.y), dup2(b0.z), dup2(b0.w),
                                    dup2(b1.x), dup2(b1.y), dup2(b1.z), dup2(b1.w)};
        #pragma unroll
        for (int p = 0; p < 4; p++)
            #pragma unroll
            for (int j = 0; j < 8; j++)
                acc2[p][j] = ffma2(ap[p], bd[j], acc2[p][j]);
    }
}

__global__ void __launch_bounds__(256, 2)
gemm128_kernel(const float* __restrict__ xext, int use_ext,
               const float* __restrict__ W,
               const float* __restrict__ asrc,
               const float* __restrict__ adst, int n) {
    __shared__ SBuf buf[2];
    const float* A = use_ext ? xext : g_feat;
    int t = threadIdx.x;
    int n0 = blockIdx.x * 128;
    int rowg = t >> 4;
    int colg = t & 15;
    int lrow = t >> 1;
    int lk4  = (t & 1) * 4;
    bool rvalid = (n0 + lrow) < n;
    const float* arow = A + (size_t)(n0 + lrow) * F;
    const float* wrow = W + (size_t)lrow * F;

    unsigned long long acc2[4][8];
    #pragma unroll
    for (int p = 0; p < 4; p++)
        #pragma unroll
        for (int j = 0; j < 8; j++) acc2[p][j] = 0ULL;

    const float4 zf4 = make_float4(0.f, 0.f, 0.f, 0.f);
    float4 av = rvalid ? *(const float4*)(arow + lk4) : zf4;
    float4 wv = *(const float4*)(wrow + lk4);
    gemm_store_slab(buf[0], lrow, lk4, av, wv);
    __syncthreads();

    // 16 slabs of BK=8, processed in double-buffered pairs
    for (int s = 0; s < 8; s++) {
        int k1 = 2 * s * 8 + 8;                 // slab 2s+1 base
        av = rvalid ? *(const float4*)(arow + k1 + lk4) : zf4;
        wv = *(const float4*)(wrow + k1 + lk4);
        gemm_compute_slab(buf[0], rowg, colg, acc2);
        gemm_store_slab(buf[1], lrow, lk4, av, wv);
        __syncthreads();
        if (s < 7) {
            int k2 = k1 + 8;                    // slab 2s+2
            av = rvalid ? *(const float4*)(arow + k2 + lk4) : zf4;
            wv = *(const float4*)(wrow + k2 + lk4);
        }
        gemm_compute_slab(buf[1], rowg, colg, acc2);
        if (s < 7) {
            gemm_store_slab(buf[0], lrow, lk4, av, wv);
            __syncthreads();
        }
    }

    float acc[8][8];
    #pragma unroll
    for (int p = 0; p < 4; p++)
        #pragma unroll
        for (int j = 0; j < 8; j++) {
            float2 f = *reinterpret_cast<float2*>(&acc2[p][j]);
            acc[2 * p][j] = f.x;
            acc[2 * p + 1][j] = f.y;
        }

    #pragma unroll
    for (int i = 0; i < 8; i++) {
        int row = n0 + rowg * 8 + i;
        if (row < n) {
            float4 v0 = make_float4(acc[i][0], acc[i][1], acc[i][2], acc[i][3]);
            float4 v1 = make_float4(acc[i][4], acc[i][5], acc[i][6], acc[i][7]);
            *(float4*)(g_hw + (size_t)row * F + colg * 8)     = v0;
            *(float4*)(g_hw + (size_t)row * F + colg * 8 + 4) = v1;
        }
    }

    float4 as0 = *(const float4*)(asrc + colg * 8);
    float4 as1 = *(const float4*)(asrc + colg * 8 + 4);
    float4 ad0 = *(const float4*)(adst + colg * 8);
    float4 ad1 = *(const float4*)(adst + colg * 8 + 4);
    #pragma unroll
    for (int i = 0; i < 8; i++) {
        float ps = acc[i][0] * as0.x + acc[i][1] * as0.y + acc[i][2] * as0.z + acc[i][3] * as0.w
                 + acc[i][4] * as1.x + acc[i][5] * as1.y + acc[i][6] * as1.z + acc[i][7] * as1.w;
        float pd = acc[i][0] * ad0.x + acc[i][1] * ad0.y + acc[i][2] * ad0.z + acc[i][3] * ad0.w
                 + acc[i][4] * ad1.x + acc[i][5] * ad1.y + acc[i][6] * ad1.z + acc[i][7] * ad1.w;
        ps += __shfl_down_sync(0xffffffffu, ps, 2, 4);
        ps += __shfl_down_sync(0xffffffffu, ps, 1, 4);
        pd += __shfl_down_sync(0xffffffffu, pd, 2, 4);
        pd += __shfl_down_sync(0xffffffffu, pd, 1, 4);
        int row = n0 + rowg * 8 + i;
        if ((colg & 3) == 0 && row < n) {
            g_als[row * HEADS + (colg >> 2)] = ps;
            g_ald[row * HEADS + (colg >> 2)] = pd;
        }
    }
}

// ---------------- aggregation (R3 fp32 version) ----------------
__global__ void agg_kernel(const float* __restrict__ bias,
                           float* __restrict__ outext, int use_ext,
                           int apply_elu, int n) {
    __shared__ float4 s_w[8][32];
    __shared__ int    s_sn[8][32];
    int wip = threadIdx.x >> 5;
    int node = blockIdx.x * 8 + wip;
    if (node >= n) return;
    int lane = threadIdx.x & 31;
    int hd = lane >> 3;
    int j0 = g_off[node], j1 = g_off[node + 1];
    float4 ald = *(const float4*)(g_ald + node * HEADS);
    float4 ssum = make_float4(0.f, 0.f, 0.f, 0.f);
    float4 acc  = make_float4(0.f, 0.f, 0.f, 0.f);

    for (int base = j0; base < j1; base += 32) {
        int j = base + lane;
        float4 w4 = make_float4(0.f, 0.f, 0.f, 0.f);
        int sn = 0;
        if (j < j1) {
            sn = g_ssrc[j];
            float4 al = *(const float4*)(g_als + sn * HEADS);
            float e0 = al.x + ald.x; e0 = fmaxf(e0, 0.2f * e0);
            float e1 = al.y + ald.y; e1 = fmaxf(e1, 0.2f * e1);
            float e2 = al.z + ald.z; e2 = fmaxf(e2, 0.2f * e2);
            float e3 = al.w + ald.w; e3 = fmaxf(e3, 0.2f * e3);
            w4.x = __expf(e0); w4.y = __expf(e1);
            w4.z = __expf(e2); w4.w = __expf(e3);
            ssum.x += w4.x; ssum.y += w4.y; ssum.z += w4.z; ssum.w += w4.w;
        }
        s_sn[wip][lane] = sn;
        s_w[wip][lane]  = w4;
        __syncwarp();
        int cnt = min(32, j1 - base);
        const float* wj = &s_w[wip][0].x;
        #pragma unroll 4
        for (int jj = 0; jj < cnt; jj++) {
            int s = s_sn[wip][jj];
            float wgt = wj[jj * 4 + hd];
            const float4 hv = *(const float4*)(g_hw + (size_t)s * F + lane * 4);
            acc.x = fmaf(wgt, hv.x, acc.x);
            acc.y = fmaf(wgt, hv.y, acc.y);
            acc.z = fmaf(wgt, hv.z, acc.z);
            acc.w = fmaf(wgt, hv.w, acc.w);
        }
        __syncwarp();
    }

    #pragma unroll
    for (int d = 16; d > 0; d >>= 1) {
        ssum.x += __shfl_xor_sync(0xffffffffu, ssum.x, d);
        ssum.y += __shfl_xor_sync(0xffffffffu, ssum.y, d);
        ssum.z += __shfl_xor_sync(0xffffffffu, ssum.z, d);
        ssum.w += __shfl_xor_sync(0xffffffffu, ssum.w, d);
    }
    float sh = (hd == 0) ? ssum.x : (hd == 1) ? ssum.y : (hd == 2) ? ssum.z : ssum.w;
    float inv = 1.f / (sh + 1e-16f);
    float4 bv = *(const float4*)(bias + lane * 4);
    float4 o;
    o.x = fmaf(acc.x, inv, bv.x);
    o.y = fmaf(acc.y, inv, bv.y);
    o.z = fmaf(acc.z, inv, bv.z);
    o.w = fmaf(acc.w, inv, bv.w);
    if (apply_elu) {
        o.x = o.x > 0.f ? o.x : expm1f(o.x);
        o.y = o.y > 0.f ? o.y : expm1f(o.y);
        o.z = o.z > 0.f ? o.z : expm1f(o.z);
        o.w = o.w > 0.f ? o.w : expm1f(o.w);
    }
    float* outp = use_ext ? outext : g_feat;
    *(float4*)(outp + (size_t)node * F + lane * 4) = o;
}

// ---------------- launch ----------------
extern "C" void kernel_launch(void* const* d_in, const int* in_sizes, int n_in,
                              void* d_out, int out_size) {
    const float* x   = (const float*)d_in[0];
    const int*   src = (const int*)d_in[1];
    const int*   dst = (const int*)d_in[2];
    const int n = in_sizes[0] / F;
    const int e = in_sizes[1];

    const int gemm_grid = (n + 127) / 128;
    const int agg_grid  = (n + 7) / 8;

    // gemm0 hoisted so the profiler's fixed sample slot lands on the GEMM
    zero_deg_kernel<<<(n + 255) / 256, 256>>>(n);
    hist_kernel<<<(e + 255) / 256, 256>>>(dst, e);
    scan_kernel<<<1, 1024>>>(n);
    gemm128_kernel<<<gemm_grid, 256>>>(x, 1, (const float*)d_in[3],
                                       (const float*)d_in[4], (const float*)d_in[5], n);
    scatter_kernel<<<(e + 255) / 256, 256>>>(src, dst, e);

    for (int l = 0; l < 3; l++) {
        const float* W    = (const float*)d_in[3 + 4 * l];
        const float* asrc = (const float*)d_in[4 + 4 * l];
        const float* adst = (const float*)d_in[5 + 4 * l];
        const float* b    = (const float*)d_in[6 + 4 * l];
        if (l > 0)
            gemm128_kernel<<<gemm_grid, 256>>>(x, 0, W, asrc, adst, n);
        int last = (l == 2);
        agg_kernel<<<agg_grid, 256>>>(b, (float*)d_out, last, last ? 0 : 1, n);
    }
}

// round 7
// speedup vs baseline: 1.6927x; 1.4318x over previous
#include <cuda_runtime.h>
#include <cuda_fp16.h>
#include <math.h>

#define NN 50000
#define EE 850000
#define F  128
#define HEADS 4

// ---------------- scratch ----------------
__device__ float g_hw[NN * F];
__device__ float g_feat[NN * F];
__device__ float g_als[NN * HEADS];
__device__ float g_ald[NN * HEADS];
__device__ int   g_deg[NN];
__device__ int   g_off[NN + 1];
__device__ int   g_cur[NN];
__device__ int   g_ssrc[EE];

// ---------------- CSR build ----------------
__global__ void zero_deg_kernel(int n) {
    int i = blockIdx.x * blockDim.x + threadIdx.x;
    if (i < n) g_deg[i] = 0;
}

__global__ void hist_kernel(const int* __restrict__ dst, int e) {
    int i = blockIdx.x * blockDim.x + threadIdx.x;
    if (i < e) atomicAdd(&g_deg[dst[i]], 1);
}

__global__ void scan_kernel(int n) {
    __shared__ int wsum[32];
    __shared__ int s_total;
    int t = threadIdx.x, lane = t & 31, wid = t >> 5;
    int carry = 0;
    for (int base = 0; base < n; base += 1024) {
        int idx = base + t;
        int v = (idx < n) ? g_deg[idx] : 0;
        int x = v;
        #pragma unroll
        for (int d = 1; d < 32; d <<= 1) {
            int y = __shfl_up_sync(0xffffffffu, x, d);
            if (lane >= d) x += y;
        }
        if (lane == 31) wsum[wid] = x;
        __syncthreads();
        if (wid == 0) {
            int w = wsum[lane];
            int xs = w;
            #pragma unroll
            for (int d = 1; d < 32; d <<= 1) {
                int y = __shfl_up_sync(0xffffffffu, xs, d);
                if (lane >= d) xs += y;
            }
            wsum[lane] = xs - w;
            if (lane == 31) s_total = xs;
        }
        __syncthreads();
        int excl = carry + wsum[wid] + (x - v);
        if (idx < n) { g_off[idx] = excl; g_cur[idx] = excl; }
        carry += s_total;
        __syncthreads();
    }
    if (t == 0) g_off[n] = carry;
}

__global__ void scatter_kernel(const int* __restrict__ src,
                               const int* __restrict__ dst, int e) {
    int i = blockIdx.x * blockDim.x + threadIdx.x;
    if (i < e) {
        int d = dst[i];
        int p = atomicAdd(&g_cur[d], 1);
        g_ssrc[p] = src[i];
    }
}

// ---------------- MMA helpers ----------------
__device__ __forceinline__ void ldsm_x4(unsigned* r, unsigned addr) {
    asm volatile("ldmatrix.sync.aligned.m8n8.x4.shared.b16 {%0,%1,%2,%3}, [%4];"
        : "=r"(r[0]), "=r"(r[1]), "=r"(r[2]), "=r"(r[3]) : "r"(addr));
}
__device__ __forceinline__ void mma16816(float* d, const unsigned* a,
                                         unsigned b0, unsigned b1) {
    asm volatile("mma.sync.aligned.m16n8k16.row.col.f32.f16.f16.f32 "
        "{%0,%1,%2,%3}, {%4,%5,%6,%7}, {%8,%9}, {%0,%1,%2,%3};"
        : "+f"(d[0]), "+f"(d[1]), "+f"(d[2]), "+f"(d[3])
        : "r"(a[0]), "r"(a[1]), "r"(a[2]), "r"(a[3]), "r"(b0), "r"(b1));
}

// ---------------- GEMM: tensor-core fp16 inputs, fp32 accum ----------------
// block = 128x128 tile, K=128 fully staged in smem; 8 warps, each 16 rows x 128 cols.
#define STRH 136   // smem halves per row
#define GEMM_SMEM (2 * 128 * STRH * 2)

__global__ void __launch_bounds__(256)
gemm128_kernel(const float* __restrict__ xext, int use_ext,
               const float* __restrict__ W,
               const float* __restrict__ asrc,
               const float* __restrict__ adst, int n) {
    extern __shared__ char smem[];
    __half* sA = (__half*)smem;
    __half* sW = (__half*)(smem + 128 * STRH * 2);
    const float* A = use_ext ? xext : g_feat;
    int t = threadIdx.x;
    int n0 = blockIdx.x * 128;
    const float4 zf4 = make_float4(0.f, 0.f, 0.f, 0.f);

    // fill: fp32 global -> fp16 smem (A tile + W)
    #pragma unroll
    for (int it = 0; it < 16; it++) {
        int idx = it * 256 + t;          // 0..4095 float4 slots
        int row = idx >> 5;
        int c4 = (idx & 31) * 4;
        float4 v = (n0 + row < n) ? *(const float4*)(A + (size_t)(n0 + row) * F + c4) : zf4;
        __half2* da = (__half2*)(sA + row * STRH + c4);
        da[0] = __floats2half2_rn(v.x, v.y);
        da[1] = __floats2half2_rn(v.z, v.w);
        float4 w = *(const float4*)(W + (size_t)row * F + c4);
        __half2* dw = (__half2*)(sW + row * STRH + c4);
        dw[0] = __floats2half2_rn(w.x, w.y);
        dw[1] = __floats2half2_rn(w.z, w.w);
    }
    __syncthreads();

    int wid = t >> 5, lane = t & 31;
    int M0 = wid * 16;

    float d[16][4];
    #pragma unroll
    for (int j = 0; j < 16; j++)
        #pragma unroll
        for (int q = 0; q < 4; q++) d[j][q] = 0.f;

    unsigned sAu = (unsigned)__cvta_generic_to_shared(sA);
    unsigned sWu = (unsigned)__cvta_generic_to_shared(sW);
    // A: lanes 0-15 -> rows M0+0..15 @ k0; lanes 16-31 -> same rows @ k8
    unsigned aBase = sAu + ((M0 + (lane & 15)) * STRH + (lane >> 4) * 8) * 2;
    // B (non-trans; W is [n][k] row-major):
    //   lanes 0-7  -> n 0-7  @ k0 ; lanes 8-15  -> n 0-7  @ k8
    //   lanes 16-23-> n 8-15 @ k0 ; lanes 24-31 -> n 8-15 @ k8
    unsigned bBase = sWu + (((lane & 7) + ((lane >> 4) & 1) * 8) * STRH
                            + ((lane >> 3) & 1) * 8) * 2;

    #pragma unroll
    for (int ks = 0; ks < 8; ks++) {        // K step = 16
        unsigned a[4];
        ldsm_x4(a, aBase + ks * 32);
        #pragma unroll
        for (int g = 0; g < 8; g++) {       // 16 cols per group
            unsigned b[4];
            ldsm_x4(b, bBase + g * (16 * STRH * 2) + ks * 32);
            mma16816(d[2 * g],     a, b[0], b[1]);
            mma16816(d[2 * g + 1], a, b[2], b[3]);
        }
    }

    // epilogue: store h (fp32) + fused attention logits
    int r0l = M0 + (lane >> 2);
    int grow0 = n0 + r0l, grow1 = grow0 + 8;
    int c2 = (lane & 3) * 2;
    bool v0 = grow0 < n, v1 = grow1 < n;

    float ps0[4] = {0, 0, 0, 0}, pd0[4] = {0, 0, 0, 0};
    float ps1[4] = {0, 0, 0, 0}, pd1[4] = {0, 0, 0, 0};
    #pragma unroll
    for (int j = 0; j < 16; j++) {
        const int head = j >> 2;
        float2 as = *(const float2*)(asrc + j * 8 + c2);
        float2 ad = *(const float2*)(adst + j * 8 + c2);
        ps0[head] += d[j][0] * as.x + d[j][1] * as.y;
        pd0[head] += d[j][0] * ad.x + d[j][1] * ad.y;
        ps1[head] += d[j][2] * as.x + d[j][3] * as.y;
        pd1[head] += d[j][2] * ad.x + d[j][3] * ad.y;
        if (v0) *(float2*)(g_hw + (size_t)grow0 * F + j * 8 + c2) = make_float2(d[j][0], d[j][1]);
        if (v1) *(float2*)(g_hw + (size_t)grow1 * F + j * 8 + c2) = make_float2(d[j][2], d[j][3]);
    }
    #pragma unroll
    for (int s = 1; s < 4; s <<= 1) {
        #pragma unroll
        for (int h = 0; h < 4; h++) {
            ps0[h] += __shfl_xor_sync(0xffffffffu, ps0[h], s);
            pd0[h] += __shfl_xor_sync(0xffffffffu, pd0[h], s);
            ps1[h] += __shfl_xor_sync(0xffffffffu, ps1[h], s);
            pd1[h] += __shfl_xor_sync(0xffffffffu, pd1[h], s);
        }
    }
    int h = lane & 3;
    float vs0 = (h == 0) ? ps0[0] : (h == 1) ? ps0[1] : (h == 2) ? ps0[2] : ps0[3];
    float vd0 = (h == 0) ? pd0[0] : (h == 1) ? pd0[1] : (h == 2) ? pd0[2] : pd0[3];
    float vs1 = (h == 0) ? ps1[0] : (h == 1) ? ps1[1] : (h == 2) ? ps1[2] : ps1[3];
    float vd1 = (h == 0) ? pd1[0] : (h == 1) ? pd1[1] : (h == 2) ? pd1[2] : pd1[3];
    if (v0) { g_als[grow0 * HEADS + h] = vs0; g_ald[grow0 * HEADS + h] = vd0; }
    if (v1) { g_als[grow1 * HEADS + h] = vs1; g_ald[grow1 * HEADS + h] = vd1; }
}

// ---------------- aggregation (proven fp32 version) ----------------
__global__ void agg_kernel(const float* __restrict__ bias,
                           float* __restrict__ outext, int use_ext,
                           int apply_elu, int n) {
    __shared__ float4 s_w[8][32];
    __shared__ int    s_sn[8][32];
    int wip = threadIdx.x >> 5;
    int node = blockIdx.x * 8 + wip;
    if (node >= n) return;
    int lane = threadIdx.x & 31;
    int hd = lane >> 3;
    int j0 = g_off[node], j1 = g_off[node + 1];
    float4 ald = *(const float4*)(g_ald + node * HEADS);
    float4 ssum = make_float4(0.f, 0.f, 0.f, 0.f);
    float4 acc  = make_float4(0.f, 0.f, 0.f, 0.f);

    for (int base = j0; base < j1; base += 32) {
        int j = base + lane;
        float4 w4 = make_float4(0.f, 0.f, 0.f, 0.f);
        int sn = 0;
        if (j < j1) {
            sn = g_ssrc[j];
            float4 al = *(const float4*)(g_als + sn * HEADS);
            float e0 = al.x + ald.x; e0 = fmaxf(e0, 0.2f * e0);
            float e1 = al.y + ald.y; e1 = fmaxf(e1, 0.2f * e1);
            float e2 = al.z + ald.z; e2 = fmaxf(e2, 0.2f * e2);
            float e3 = al.w + ald.w; e3 = fmaxf(e3, 0.2f * e3);
            w4.x = __expf(e0); w4.y = __expf(e1);
            w4.z = __expf(e2); w4.w = __expf(e3);
            ssum.x += w4.x; ssum.y += w4.y; ssum.z += w4.z; ssum.w += w4.w;
        }
        s_sn[wip][lane] = sn;
        s_w[wip][lane]  = w4;
        __syncwarp();
        int cnt = min(32, j1 - base);
        const float* wj = &s_w[wip][0].x;
        #pragma unroll 4
        for (int jj = 0; jj < cnt; jj++) {
            int s = s_sn[wip][jj];
            float wgt = wj[jj * 4 + hd];
            const float4 hv = *(const float4*)(g_hw + (size_t)s * F + lane * 4);
            acc.x = fmaf(wgt, hv.x, acc.x);
            acc.y = fmaf(wgt, hv.y, acc.y);
            acc.z = fmaf(wgt, hv.z, acc.z);
            acc.w = fmaf(wgt, hv.w, acc.w);
        }
        __syncwarp();
    }

    #pragma unroll
    for (int d = 16; d > 0; d >>= 1) {
        ssum.x += __shfl_xor_sync(0xffffffffu, ssum.x, d);
        ssum.y += __shfl_xor_sync(0xffffffffu, ssum.y, d);
        ssum.z += __shfl_xor_sync(0xffffffffu, ssum.z, d);
        ssum.w += __shfl_xor_sync(0xffffffffu, ssum.w, d);
    }
    float sh = (hd == 0) ? ssum.x : (hd == 1) ? ssum.y : (hd == 2) ? ssum.z : ssum.w;
    float inv = 1.f / (sh + 1e-16f);
    float4 bv = *(const float4*)(bias + lane * 4);
    float4 o;
    o.x = fmaf(acc.x, inv, bv.x);
    o.y = fmaf(acc.y, inv, bv.y);
    o.z = fmaf(acc.z, inv, bv.z);
    o.w = fmaf(acc.w, inv, bv.w);
    if (apply_elu) {
        o.x = o.x > 0.f ? o.x : expm1f(o.x);
        o.y = o.y > 0.f ? o.y : expm1f(o.y);
        o.z = o.z > 0.f ? o.z : expm1f(o.z);
        o.w = o.w > 0.f ? o.w : expm1f(o.w);
    }
    float* outp = use_ext ? outext : g_feat;
    *(float4*)(outp + (size_t)node * F + lane * 4) = o;
}

// ---------------- launch ----------------
extern "C" void kernel_launch(void* const* d_in, const int* in_sizes, int n_in,
                              void* d_out, int out_size) {
    const float* x   = (const float*)d_in[0];
    const int*   src = (const int*)d_in[1];
    const int*   dst = (const int*)d_in[2];
    const int n = in_sizes[0] / F;
    const int e = in_sizes[1];

    const int gemm_grid = (n + 127) / 128;
    const int agg_grid  = (n + 7) / 8;

    cudaFuncSetAttribute(gemm128_kernel,
                         cudaFuncAttributeMaxDynamicSharedMemorySize, GEMM_SMEM);

    // gemm0 hoisted so the profiler's fixed sample slot lands on the GEMM
    zero_deg_kernel<<<(n + 255) / 256, 256>>>(n);
    hist_kernel<<<(e + 255) / 256, 256>>>(dst, e);
    scan_kernel<<<1, 1024>>>(n);
    gemm128_kernel<<<gemm_grid, 256, GEMM_SMEM>>>(x, 1, (const float*)d_in[3],
                                                  (const float*)d_in[4],
                                                  (const float*)d_in[5], n);
    scatter_kernel<<<(e + 255) / 256, 256>>>(src, dst, e);

    for (int l = 0; l < 3; l++) {
        const float* W    = (const float*)d_in[3 + 4 * l];
        const float* asrc = (const float*)d_in[4 + 4 * l];
        const float* adst = (const float*)d_in[5 + 4 * l];
        const float* b    = (const float*)d_in[6 + 4 * l];
        if (l > 0)
            gemm128_kernel<<<gemm_grid, 256, GEMM_SMEM>>>(x, 0, W, asrc, adst, n);
        int last = (l == 2);
        agg_kernel<<<agg_grid, 256>>>(b, (float*)d_out, last, last ? 0 : 1, n);
    }
}